// round 1
// baseline (speedup 1.0000x reference)
#include <cuda_runtime.h>
#include <math.h>

#define S  20
#define SS 400

__device__ __forceinline__ float softplusf(float x) {
    // numerically stable: max(x,0) + log1p(exp(-|x|)) == logaddexp(x, 0)
    return fmaxf(x, 0.0f) + log1pf(expf(-fabsf(x)));
}

__device__ __forceinline__ float wred_max(float v) {
#pragma unroll
    for (int o = 16; o > 0; o >>= 1) v = fmaxf(v, __shfl_xor_sync(0xffffffffu, v, o));
    return v;
}
__device__ __forceinline__ float wred_sum(float v) {
#pragma unroll
    for (int o = 16; o > 0; o >>= 1) v += __shfl_xor_sync(0xffffffffu, v, o);
    return v;
}

// One block per (m,b). Warp kk handles rate-category matrix k=kk.
// expm via scaling-and-squaring + Taylor(J), matrices held column-in-registers,
// multiplier matrix broadcast from shared (conflict-free LDS).
template <int K>
__global__ void __launch_bounds__(32 * K)
ancprobs_kernel(const int*   __restrict__ seq,    // (m,b,L)
                const int*   __restrict__ ridx,   // (m,b)
                const float* __restrict__ tauk,   // (m,num_rates)
                const float* __restrict__ exch,   // (m,K,20,20)
                const float* __restrict__ eq,     // (m,K,20)
                float*       __restrict__ out,    // (m,b,L,K,20)
                int b, int L, int num_rates)
{
    __shared__ __align__(16) float sQ[K][SS];   // column-major: Q[i][t] at [t*20+i]
    __shared__ __align__(16) float sP[K][SS];   // row-major final P
    __shared__ float sp[K][S];

    const int bid  = blockIdx.x;              // flattened (m,b)
    const int mi   = bid / b;
    const int bi   = bid - mi * b;
    const int kk   = threadIdx.x >> 5;
    const int lane = threadIdx.x & 31;

    // ---------------- build Q for (mi, kk) ----------------
    const float* Ek = exch + (size_t)(mi * K + kk) * SS;
    const float* ek = eq   + (size_t)(mi * K + kk) * S;

    // softmax p
    float x  = (lane < S) ? ek[lane] : -3.0e38f;
    float mx = wred_max(x);
    float ex = (lane < S) ? expf(x - mx) : 0.0f;
    float sm = wred_sum(ex);
    float pl = ex / sm;
    if (lane < S) sp[kk][lane] = pl;
    __syncwarp();

    // row lane of Q (before normalization)
    float qrow[S];
    float diag = 0.0f;
    if (lane < S) {
#pragma unroll
        for (int j = 0; j < S; j++) {
            float r = (j == lane) ? 0.0f
                                  : softplusf(0.5f * (Ek[lane * S + j] + Ek[j * S + lane]));
            float q = r * sp[kk][j];
            qrow[j] = q;
            diag += q;
        }
        qrow[lane] = -diag;   // R diag is zero, so Q[i][i] = -rowsum
    }
    float mue = wred_sum((lane < S) ? pl * diag : 0.0f);
    float inv = 1.0f / fmaxf(mue, 1e-16f);
    if (lane < S) {
#pragma unroll
        for (int j = 0; j < S; j++) sQ[kk][j * S + lane] = qrow[j] * inv;  // column-major
    }
    // inf-norm of Q: row sum of |Q| = 2*diag*inv
    float an = wred_max((lane < S) ? 2.0f * diag * inv : 0.0f);

    // tau for this (m,b)
    const int   r0  = ridx[mi * b + bi];
    const float tau = softplusf(tauk[mi * num_rates + r0]);

    // scaling: want ||tau*Q|| * 2^-sc <= 0.5
    float nrm = tau * an;
    int sc = 0;
    while (nrm > 0.5f && sc < 40) { nrm *= 0.5f; sc++; }
    const float factor = ldexpf(tau, -sc);   // M = factor * Q (kept implicit)
    __syncwarp();

    // ---------------- Taylor series: E = I + M + M^2/2! + ... ----------------
    float t[S], e[S];
    const int col = (lane < S) ? lane : 0;
#pragma unroll
    for (int i = 0; i < S; i++) {
        float q = sQ[kk][col * S + i];
        t[i] = factor * q;
        e[i] = t[i] + ((i == lane) ? 1.0f : 0.0f);
    }

    const int J = 12;
#pragma unroll 1
    for (int j = 2; j <= J; j++) {
        const float coef = factor / (float)j;
        float c[S];
#pragma unroll
        for (int i = 0; i < S; i++) c[i] = 0.0f;
#pragma unroll
        for (int tt = 0; tt < S; tt++) {
            const float tv = t[tt];
#pragma unroll
            for (int i = 0; i < S; i++) c[i] = fmaf(sQ[kk][tt * S + i], tv, c[i]);
        }
#pragma unroll
        for (int i = 0; i < S; i++) { t[i] = c[i] * coef; e[i] += t[i]; }
    }

    // ---------------- squarings: E <- E*E, sc times ----------------
#pragma unroll 1
    for (int r = 0; r < sc; r++) {
        __syncwarp();
        if (lane < S) {
#pragma unroll
            for (int i = 0; i < S; i++) sQ[kk][lane * S + i] = e[i];  // E column-major
        }
        __syncwarp();
        float c[S];
#pragma unroll
        for (int i = 0; i < S; i++) c[i] = 0.0f;
#pragma unroll
        for (int tt = 0; tt < S; tt++) {
            const float tv = e[tt];
#pragma unroll
            for (int i = 0; i < S; i++) c[i] = fmaf(sQ[kk][tt * S + i], tv, c[i]);
        }
#pragma unroll
        for (int i = 0; i < S; i++) e[i] = c[i];
    }

    // store P row-major: P[i][lane] = e[i]
    if (lane < S) {
#pragma unroll
        for (int i = 0; i < S; i++) sP[kk][i * S + lane] = e[i];
    }
    __syncthreads();

    // ---------------- gather: out[m,b,l,k,:] = P[k][seq[l],:] ----------------
    const int*    seqrow = seq + (size_t)bid * L;
    const int     nf4    = L * K * 5;                 // float4 count for this (m,b)
    float4*       out4   = reinterpret_cast<float4*>(out) + (size_t)bid * nf4;

    for (int g = threadIdx.x; g < nf4; g += 32 * K) {
        const int l  = g / (K * 5);
        const int j  = g - l * (K * 5);
        const int kq = j / 5;
        const int s4 = j - kq * 5;
        const int s0 = seqrow[l];
        out4[g] = reinterpret_cast<const float4*>(&sP[kq][0])[s0 * 5 + s4];
    }
}

extern "C" void kernel_launch(void* const* d_in, const int* in_sizes, int n_in,
                              void* d_out, int out_size)
{
    const int*   seq  = (const int*)  d_in[0];  // sequences (m,b,L) int32
    const int*   ridx = (const int*)  d_in[1];  // rate_indices (m,b) int32
    const float* tauk = (const float*)d_in[2];  // tau_kernel (m,num_rates)
    const float* exch = (const float*)d_in[3];  // exchangeability (m,k,20,20)
    const float* eq   = (const float*)d_in[4];  // equilibrium (m,k,20)
    float*       out  = (float*)d_out;

    const int n_seq = in_sizes[0];
    const int n_ri  = in_sizes[1];
    const int n_tau = in_sizes[2];
    const int n_eq  = in_sizes[4];

    const int mk = n_eq / S;                       // m*k
    const int k  = out_size / (n_seq * S);         // out = m*b*L*k*S
    const int m  = mk / k;
    const int b  = n_ri / m;
    const int L  = n_seq / n_ri;
    const int nr = n_tau / m;

    const int grid = m * b;
    switch (k) {
        case 1: ancprobs_kernel<1><<<grid, 32 * 1>>>(seq, ridx, tauk, exch, eq, out, b, L, nr); break;
        case 2: ancprobs_kernel<2><<<grid, 32 * 2>>>(seq, ridx, tauk, exch, eq, out, b, L, nr); break;
        case 3: ancprobs_kernel<3><<<grid, 32 * 3>>>(seq, ridx, tauk, exch, eq, out, b, L, nr); break;
        case 4: ancprobs_kernel<4><<<grid, 32 * 4>>>(seq, ridx, tauk, exch, eq, out, b, L, nr); break;
        default: break; // dataset has k=2
    }
}